// round 1
// baseline (speedup 1.0000x reference)
#include <cuda_runtime.h>
#include <cuda_bf16.h>

#define BATCH 4
#define SEQ   2048
#define DMODEL 1024
#define NHEADS 16
#define DK    64

// ---------------- scratch (static device globals; no allocation) ------------
__device__ float g_Q[BATCH * NHEADS * SEQ * DK];     // [B,H,S,Dk]
__device__ float g_K[BATCH * NHEADS * SEQ * DK];
__device__ float g_V[BATCH * NHEADS * SEQ * DK];
__device__ float g_ctx[BATCH * SEQ * DMODEL];        // [B,S,D]

// ---------------- generic 128x128x8 fp32 SGEMM body -------------------------
// X: [M=8192, K=1024] row-major, W: [1024, 1024] row-major, bias: [1024]
// LAYOUT 0: out[m*1024 + n]
// LAYOUT 1: out[((b*H + h)*S + s)*64 + dk]   (QKV scatter)
template <int LAYOUT>
__device__ __forceinline__ void gemm_body(
    const float* __restrict__ X, const float* __restrict__ W,
    const float* __restrict__ bias, float* __restrict__ out)
{
    __shared__ float Xs[8][128];
    __shared__ float Ws[8][128];

    const int tid = threadIdx.x;
    const int m0 = blockIdx.y * 128;
    const int n0 = blockIdx.x * 128;

    const int xr = tid >> 1;           // 0..127
    const int xc = (tid & 1) * 4;      // 0 or 4
    const int wr = tid >> 5;           // 0..7
    const int wc = (tid & 31) * 4;     // 0..124

    const int row_t = (tid >> 4) * 8;  // 0..120
    const int col_t = (tid & 15) * 8;  // 0..120

    float acc[8][8];
#pragma unroll
    for (int i = 0; i < 8; i++)
#pragma unroll
        for (int j = 0; j < 8; j++) acc[i][j] = 0.f;

    for (int k0 = 0; k0 < DMODEL; k0 += 8) {
        float4 xv = *(const float4*)&X[(size_t)(m0 + xr) * DMODEL + k0 + xc];
        Xs[xc + 0][xr] = xv.x;
        Xs[xc + 1][xr] = xv.y;
        Xs[xc + 2][xr] = xv.z;
        Xs[xc + 3][xr] = xv.w;
        float4 wv = *(const float4*)&W[(size_t)(k0 + wr) * DMODEL + n0 + wc];
        *(float4*)&Ws[wr][wc] = wv;
        __syncthreads();

#pragma unroll
        for (int kk = 0; kk < 8; kk++) {
            float a[8], b[8];
#pragma unroll
            for (int i = 0; i < 8; i++) a[i] = Xs[kk][row_t + i];
#pragma unroll
            for (int j = 0; j < 8; j++) b[j] = Ws[kk][col_t + j];
#pragma unroll
            for (int i = 0; i < 8; i++)
#pragma unroll
                for (int j = 0; j < 8; j++) acc[i][j] += a[i] * b[j];
        }
        __syncthreads();
    }

#pragma unroll
    for (int i = 0; i < 8; i++) {
        const int m = m0 + row_t + i;
        const int b = m >> 11;        // /SEQ
        const int s = m & (SEQ - 1);
#pragma unroll
        for (int j = 0; j < 8; j++) {
            const int n = n0 + col_t + j;
            const float v = acc[i][j] + bias[n];
            if (LAYOUT == 0) {
                out[(size_t)m * DMODEL + n] = v;
            } else {
                const int h = n >> 6;
                const int dk = n & 63;
                out[(((size_t)(b * NHEADS + h) * SEQ + s) << 6) + dk] = v;
            }
        }
    }
}

__global__ __launch_bounds__(256, 2) void qkv_gemm(
    const float* __restrict__ x,
    const float* __restrict__ wq, const float* __restrict__ bq,
    const float* __restrict__ wk, const float* __restrict__ bk,
    const float* __restrict__ wv, const float* __restrict__ bv)
{
    const float* W;
    const float* bias;
    float* out;
    if (blockIdx.z == 0)      { W = wq; bias = bq; out = g_Q; }
    else if (blockIdx.z == 1) { W = wk; bias = bk; out = g_K; }
    else                      { W = wv; bias = bv; out = g_V; }
    gemm_body<1>(x, W, bias, out);
}

__global__ __launch_bounds__(256, 2) void out_gemm(
    const float* __restrict__ wo, const float* __restrict__ bo,
    float* __restrict__ out)
{
    gemm_body<0>(g_ctx, wo, bo, out);
}

// ---------------- flash attention, fp32, 64x64 tiles -------------------------
// grid: (SEQ/64, B*H), block 256 threads
// smem: Qs[64][65] | KVs[64][65] | Ps[64][65]  = 49,920 B (dynamic)
__global__ __launch_bounds__(256) void flash_attn(const int* __restrict__ mask)
{
    extern __shared__ float sm[];
    float* Qs = sm;                 // 64*65
    float* KVs = sm + 64 * 65;      // K then V
    float* Ps = sm + 2 * 64 * 65;

    const int bh = blockIdx.y;
    const int b = bh >> 4;
    const int q0 = blockIdx.x * 64;
    const int tid = threadIdx.x;

    const float* Qp = g_Q + (size_t)bh * SEQ * DK;
    const float* Kp = g_K + (size_t)bh * SEQ * DK;
    const float* Vp = g_V + (size_t)bh * SEQ * DK;

    // load Q tile (64x64 floats = 1024 float4)
#pragma unroll
    for (int i = 0; i < 4; i++) {
        int id = tid + i * 256;
        int r = id >> 4;
        int c = (id & 15) << 2;
        float4 v = *(const float4*)&Qp[(size_t)(q0 + r) * DK + c];
        float* dst = &Qs[r * 65 + c];
        dst[0] = v.x; dst[1] = v.y; dst[2] = v.z; dst[3] = v.w;
    }

    const int ty = tid >> 3;      // 0..31 -> 2 query rows each
    const int tx = tid & 7;       // 0..7  -> 8 key cols each
    const int r0 = ty * 2;
    const int r1 = r0 + 1;

    float mrow0 = -1e30f, mrow1 = -1e30f;
    float l0 = 0.f, l1 = 0.f;
    float O0[8], O1[8];
#pragma unroll
    for (int j = 0; j < 8; j++) { O0[j] = 0.f; O1[j] = 0.f; }

    const int* mbase = mask + b * SEQ;

    for (int kt = 0; kt < SEQ / 64; kt++) {
        const int k0 = kt * 64;

        __syncthreads();   // previous PV done reading KVs
        // load K tile
#pragma unroll
        for (int i = 0; i < 4; i++) {
            int id = tid + i * 256;
            int r = id >> 4;
            int c = (id & 15) << 2;
            float4 v = *(const float4*)&Kp[(size_t)(k0 + r) * DK + c];
            float* dst = &KVs[r * 65 + c];
            dst[0] = v.x; dst[1] = v.y; dst[2] = v.z; dst[3] = v.w;
        }
        __syncthreads();

        // scores: 2 rows x 8 cols per thread
        float s0[8], s1[8];
#pragma unroll
        for (int j = 0; j < 8; j++) { s0[j] = 0.f; s1[j] = 0.f; }
#pragma unroll 8
        for (int d = 0; d < 64; d++) {
            float q0v = Qs[r0 * 65 + d];
            float q1v = Qs[r1 * 65 + d];
#pragma unroll
            for (int j = 0; j < 8; j++) {
                float kv = KVs[(tx * 8 + j) * 65 + d];
                s0[j] += q0v * kv;
                s1[j] += q1v * kv;
            }
        }
#pragma unroll
        for (int j = 0; j < 8; j++) {
            float a = s0[j] * 0.125f;   // 1/sqrt(64)
            float c = s1[j] * 0.125f;
            if (mbase[k0 + tx * 8 + j] == 0) { a = -1e9f; c = -1e9f; }
            s0[j] = a; s1[j] = c;
        }

        // row max (reduce over the 8 tx lanes)
        float mt0 = s0[0], mt1 = s1[0];
#pragma unroll
        for (int j = 1; j < 8; j++) { mt0 = fmaxf(mt0, s0[j]); mt1 = fmaxf(mt1, s1[j]); }
#pragma unroll
        for (int off = 1; off < 8; off <<= 1) {
            mt0 = fmaxf(mt0, __shfl_xor_sync(0xffffffffu, mt0, off));
            mt1 = fmaxf(mt1, __shfl_xor_sync(0xffffffffu, mt1, off));
        }
        float mn0 = fmaxf(mrow0, mt0);
        float mn1 = fmaxf(mrow1, mt1);
        float al0 = __expf(mrow0 - mn0);
        float al1 = __expf(mrow1 - mn1);
        mrow0 = mn0; mrow1 = mn1;

        float ls0 = 0.f, ls1 = 0.f;
#pragma unroll
        for (int j = 0; j < 8; j++) {
            float p0 = __expf(s0[j] - mn0);
            float p1 = __expf(s1[j] - mn1);
            Ps[r0 * 65 + tx * 8 + j] = p0;
            Ps[r1 * 65 + tx * 8 + j] = p1;
            ls0 += p0; ls1 += p1;
        }
#pragma unroll
        for (int off = 1; off < 8; off <<= 1) {
            ls0 += __shfl_xor_sync(0xffffffffu, ls0, off);
            ls1 += __shfl_xor_sync(0xffffffffu, ls1, off);
        }
        l0 = l0 * al0 + ls0;
        l1 = l1 * al1 + ls1;
#pragma unroll
        for (int j = 0; j < 8; j++) { O0[j] *= al0; O1[j] *= al1; }

        __syncthreads();   // Ps visible to all; KVs reads done
        // load V tile into same buffer
#pragma unroll
        for (int i = 0; i < 4; i++) {
            int id = tid + i * 256;
            int r = id >> 4;
            int c = (id & 15) << 2;
            float4 v = *(const float4*)&Vp[(size_t)(k0 + r) * DK + c];
            float* dst = &KVs[r * 65 + c];
            dst[0] = v.x; dst[1] = v.y; dst[2] = v.z; dst[3] = v.w;
        }
        __syncthreads();

        // O += P @ V : each thread 2 rows x 8 d-cols
#pragma unroll 4
        for (int k = 0; k < 64; k++) {
            float p0 = Ps[r0 * 65 + k];
            float p1 = Ps[r1 * 65 + k];
#pragma unroll
            for (int j = 0; j < 8; j++) {
                float v = KVs[k * 65 + tx * 8 + j];
                O0[j] += p0 * v;
                O1[j] += p1 * v;
            }
        }
    }

    const float inv0 = 1.f / l0;
    const float inv1 = 1.f / l1;
    const int h = bh & 15;
    const size_t base0 = ((size_t)(b * SEQ + q0 + r0)) * DMODEL + h * 64 + tx * 8;
    const size_t base1 = base0 + DMODEL;
#pragma unroll
    for (int j = 0; j < 8; j++) {
        g_ctx[base0 + j] = O0[j] * inv0;
        g_ctx[base1 + j] = O1[j] * inv1;
    }
}

// ---------------- launch ------------------------------------------------------
extern "C" void kernel_launch(void* const* d_in, const int* in_sizes, int n_in,
                              void* d_out, int out_size)
{
    const float* x  = (const float*)d_in[0];
    const int* mask = (const int*)d_in[1];
    const float* wq = (const float*)d_in[2];
    const float* bq = (const float*)d_in[3];
    const float* wk = (const float*)d_in[4];
    const float* bk = (const float*)d_in[5];
    const float* wv = (const float*)d_in[6];
    const float* bv = (const float*)d_in[7];
    const float* wo = (const float*)d_in[8];
    const float* bo = (const float*)d_in[9];

    // 1) QKV projections: grid (N/128, M/128, 3)
    dim3 g1(DMODEL / 128, (BATCH * SEQ) / 128, 3);
    qkv_gemm<<<g1, 256>>>(x, wq, bq, wk, bk, wv, bv);

    // 2) flash attention
    const size_t shmem = 3 * 64 * 65 * sizeof(float);   // 49,920 B
    cudaFuncSetAttribute(flash_attn, cudaFuncAttributeMaxDynamicSharedMemorySize,
                         (int)shmem);
    flash_attn<<<dim3(SEQ / 64, BATCH * NHEADS), 256, shmem>>>(mask);

    // 3) output projection
    dim3 g3(DMODEL / 128, (BATCH * SEQ) / 128);
    out_gemm<<<g3, 256>>>(wo, bo, (float*)d_out);
}

// round 4
// speedup vs baseline: 1.2753x; 1.2753x over previous
#include <cuda_runtime.h>
#include <cuda_bf16.h>
#include <cstdint>

#define BATCH 4
#define SEQ   2048
#define DMODEL 1024
#define NHEADS 16
#define DK    64

// ---------------- scratch (static device globals; no allocation) ------------
__device__ float g_Q[BATCH * NHEADS * SEQ * DK];     // [B,H,S,Dk]
__device__ float g_K[BATCH * NHEADS * SEQ * DK];
__device__ float g_V[BATCH * NHEADS * SEQ * DK];
__device__ float g_ctx[BATCH * SEQ * DMODEL];        // [B,S,D]
// tf32-rounded copies
__device__ float g_xr[BATCH * SEQ * DMODEL];
__device__ float g_ctxr[BATCH * SEQ * DMODEL];
__device__ float g_wqr[DMODEL * DMODEL];
__device__ float g_wkr[DMODEL * DMODEL];
__device__ float g_wvr[DMODEL * DMODEL];
__device__ float g_wor[DMODEL * DMODEL];

// ---------------- tf32 rounding kernel ---------------------------------------
__device__ __forceinline__ float round_tf32(float f) {
    uint32_t r;
    asm("cvt.rna.tf32.f32 %0, %1;" : "=r"(r) : "f"(f));
    return __uint_as_float(r);
}

__global__ void round_tf32_kernel(const float* __restrict__ src,
                                  float* __restrict__ dst, int n4)
{
    int i = blockIdx.x * blockDim.x + threadIdx.x;
    if (i < n4) {
        float4 v = ((const float4*)src)[i];
        v.x = round_tf32(v.x); v.y = round_tf32(v.y);
        v.z = round_tf32(v.z); v.w = round_tf32(v.w);
        ((float4*)dst)[i] = v;
    }
}

// ---------------- tf32 mma GEMM ----------------------------------------------
// C[M=8192, N=1024] = X[M,1024] @ W[1024,1024] + bias
// CTA tile 128x256x32, 8 warps (2m x 4n), warp tile 64x64, mma m16n8k8.tf32
// LAYOUT 0: out[m*1024 + n]
// LAYOUT 1: out[((b*H+h)*S + s)*64 + dk]

#define XS_F (128 * 36)            // floats per X stage (pad 36)
#define WS_F (32 * 264)            // floats per W stage (pad 264)
#define STAGE_F (XS_F + WS_F)
#define SMEM_BYTES (2 * STAGE_F * 4)

__device__ __forceinline__ void cp_async16(uint32_t smem, const void* gmem) {
    asm volatile("cp.async.ca.shared.global [%0], [%1], 16;\n"
                 :: "r"(smem), "l"(gmem));
}

template <int LAYOUT>
__device__ __forceinline__ void gemm_tf32_body(
    const float* __restrict__ X, const float* __restrict__ W,
    const float* __restrict__ bias, float* __restrict__ out)
{
    extern __shared__ float sm[];
    const uint32_t smem_u32 = (uint32_t)__cvta_generic_to_shared(sm);

    const int tid = threadIdx.x;
    const int m0 = blockIdx.y * 128;
    const int n0 = blockIdx.x * 256;
    const int warp = tid >> 5, lane = tid & 31;
    const int g = lane >> 2, q = lane & 3;
    const int wm = (warp >> 2) * 64;   // warp m offset (0 or 64)
    const int wn = (warp & 3) * 64;    // warp n offset (0..192)

    float acc[4][8][4];
#pragma unroll
    for (int i = 0; i < 4; i++)
#pragma unroll
        for (int j = 0; j < 8; j++)
#pragma unroll
            for (int c = 0; c < 4; c++) acc[i][j][c] = 0.f;

    // load index precompute
    const int xr_[4] = { (tid + 0) >> 3, (tid + 256) >> 3, (tid + 512) >> 3, (tid + 768) >> 3 };
    const int xc_ = (tid & 7) << 2;

    auto load_tiles = [&](int kt, int stage) {
        const uint32_t base = smem_u32 + stage * (STAGE_F * 4);
        const float* Xp = X + (size_t)m0 * DMODEL + kt * 32;
#pragma unroll
        for (int i = 0; i < 4; i++) {
            int r = xr_[i];
            cp_async16(base + (uint32_t)(r * 36 + xc_) * 4,
                       Xp + (size_t)r * DMODEL + xc_);
        }
        const float* Wp = W + (size_t)(kt * 32) * DMODEL + n0;
        const uint32_t wbase = base + XS_F * 4;
#pragma unroll
        for (int i = 0; i < 8; i++) {
            int id = tid + i * 256;
            int r = id >> 6;
            int c = (id & 63) << 2;
            cp_async16(wbase + (uint32_t)(r * 264 + c) * 4,
                       Wp + (size_t)r * DMODEL + c);
        }
    };

    auto compute = [&](int stage) {
        const float* Xs = sm + stage * STAGE_F;
        const float* Ws = Xs + XS_F;
#pragma unroll
        for (int ks4 = 0; ks4 < 4; ks4++) {
            const int ks = ks4 * 8;
            uint32_t a[4][4], b[8][2];
#pragma unroll
            for (int i = 0; i < 4; i++) {
                int row = wm + i * 16 + g;
                a[i][0] = __float_as_uint(Xs[row * 36 + ks + q]);
                a[i][1] = __float_as_uint(Xs[(row + 8) * 36 + ks + q]);
                a[i][2] = __float_as_uint(Xs[row * 36 + ks + q + 4]);
                a[i][3] = __float_as_uint(Xs[(row + 8) * 36 + ks + q + 4]);
            }
#pragma unroll
            for (int j = 0; j < 8; j++) {
                int col = wn + j * 8 + g;
                b[j][0] = __float_as_uint(Ws[(ks + q) * 264 + col]);
                b[j][1] = __float_as_uint(Ws[(ks + q + 4) * 264 + col]);
            }
#pragma unroll
            for (int i = 0; i < 4; i++)
#pragma unroll
                for (int j = 0; j < 8; j++) {
                    asm volatile(
                        "mma.sync.aligned.m16n8k8.row.col.f32.tf32.tf32.f32 "
                        "{%0,%1,%2,%3}, {%4,%5,%6,%7}, {%8,%9}, {%0,%1,%2,%3};\n"
                        : "+f"(acc[i][j][0]), "+f"(acc[i][j][1]),
                          "+f"(acc[i][j][2]), "+f"(acc[i][j][3])
                        : "r"(a[i][0]), "r"(a[i][1]), "r"(a[i][2]), "r"(a[i][3]),
                          "r"(b[j][0]), "r"(b[j][1]));
                }
        }
    };

    load_tiles(0, 0);
    asm volatile("cp.async.commit_group;\n" ::);

    for (int kt = 0; kt < DMODEL / 32; kt++) {
        const int cur = kt & 1;
        if (kt < DMODEL / 32 - 1) {
            load_tiles(kt + 1, cur ^ 1);
            asm volatile("cp.async.commit_group;\n" ::);
            asm volatile("cp.async.wait_group 1;\n" ::);
        } else {
            asm volatile("cp.async.wait_group 0;\n" ::);
        }
        __syncthreads();
        compute(cur);
        __syncthreads();
    }

    // epilogue
#pragma unroll
    for (int i = 0; i < 4; i++) {
        const int mrow0 = m0 + wm + i * 16 + g;
        const int mrow1 = mrow0 + 8;
#pragma unroll
        for (int j = 0; j < 8; j++) {
            const int ncol = n0 + wn + j * 8 + q * 2;
            const float bi0 = bias[ncol], bi1 = bias[ncol + 1];
            float2 v0 = make_float2(acc[i][j][0] + bi0, acc[i][j][1] + bi1);
            float2 v1 = make_float2(acc[i][j][2] + bi0, acc[i][j][3] + bi1);
            if (LAYOUT == 0) {
                *(float2*)&out[(size_t)mrow0 * DMODEL + ncol] = v0;
                *(float2*)&out[(size_t)mrow1 * DMODEL + ncol] = v1;
            } else {
                const int h = ncol >> 6, dk = ncol & 63;
                {
                    const int b = mrow0 >> 11, s = mrow0 & (SEQ - 1);
                    *(float2*)&out[(((size_t)(b * NHEADS + h) * SEQ + s) << 6) + dk] = v0;
                }
                {
                    const int b = mrow1 >> 11, s = mrow1 & (SEQ - 1);
                    *(float2*)&out[(((size_t)(b * NHEADS + h) * SEQ + s) << 6) + dk] = v1;
                }
            }
        }
    }
}

__global__ __launch_bounds__(256, 1) void qkv_gemm_tf32(
    const float* __restrict__ bq, const float* __restrict__ bk,
    const float* __restrict__ bv)
{
    const float* W;
    const float* bias;
    float* out;
    if (blockIdx.z == 0)      { W = g_wqr; bias = bq; out = g_Q; }
    else if (blockIdx.z == 1) { W = g_wkr; bias = bk; out = g_K; }
    else                      { W = g_wvr; bias = bv; out = g_V; }
    gemm_tf32_body<1>(g_xr, W, bias, out);
}

__global__ __launch_bounds__(256, 1) void out_gemm_tf32(
    const float* __restrict__ bo, float* __restrict__ out)
{
    gemm_tf32_body<0>(g_ctxr, g_wor, bo, out);
}

// ---------------- flash attention, fp32, 64x64 tiles -------------------------
__global__ __launch_bounds__(256) void flash_attn(const int* __restrict__ mask)
{
    extern __shared__ float smf[];
    float* Qs = smf;                 // 64*65
    float* KVs = smf + 64 * 65;      // K then V
    float* Ps = smf + 2 * 64 * 65;

    const int bh = blockIdx.y;
    const int b = bh >> 4;
    const int q0 = blockIdx.x * 64;
    const int tid = threadIdx.x;

    const float* Qp = g_Q + (size_t)bh * SEQ * DK;
    const float* Kp = g_K + (size_t)bh * SEQ * DK;
    const float* Vp = g_V + (size_t)bh * SEQ * DK;

#pragma unroll
    for (int i = 0; i < 4; i++) {
        int id = tid + i * 256;
        int r = id >> 4;
        int c = (id & 15) << 2;
        float4 v = *(const float4*)&Qp[(size_t)(q0 + r) * DK + c];
        float* dst = &Qs[r * 65 + c];
        dst[0] = v.x; dst[1] = v.y; dst[2] = v.z; dst[3] = v.w;
    }

    const int ty = tid >> 3;
    const int tx = tid & 7;
    const int r0 = ty * 2;
    const int r1 = r0 + 1;

    float mrow0 = -1e30f, mrow1 = -1e30f;
    float l0 = 0.f, l1 = 0.f;
    float O0[8], O1[8];
#pragma unroll
    for (int j = 0; j < 8; j++) { O0[j] = 0.f; O1[j] = 0.f; }

    const int* mbase = mask + b * SEQ;

    for (int kt = 0; kt < SEQ / 64; kt++) {
        const int k0 = kt * 64;

        __syncthreads();
#pragma unroll
        for (int i = 0; i < 4; i++) {
            int id = tid + i * 256;
            int r = id >> 4;
            int c = (id & 15) << 2;
            float4 v = *(const float4*)&Kp[(size_t)(k0 + r) * DK + c];
            float* dst = &KVs[r * 65 + c];
            dst[0] = v.x; dst[1] = v.y; dst[2] = v.z; dst[3] = v.w;
        }
        __syncthreads();

        float s0[8], s1[8];
#pragma unroll
        for (int j = 0; j < 8; j++) { s0[j] = 0.f; s1[j] = 0.f; }
#pragma unroll 8
        for (int d = 0; d < 64; d++) {
            float q0v = Qs[r0 * 65 + d];
            float q1v = Qs[r1 * 65 + d];
#pragma unroll
            for (int j = 0; j < 8; j++) {
                float kv = KVs[(tx * 8 + j) * 65 + d];
                s0[j] += q0v * kv;
                s1[j] += q1v * kv;
            }
        }
#pragma unroll
        for (int j = 0; j < 8; j++) {
            float a = s0[j] * 0.125f;
            float c = s1[j] * 0.125f;
            if (mbase[k0 + tx * 8 + j] == 0) { a = -1e9f; c = -1e9f; }
            s0[j] = a; s1[j] = c;
        }

        float mt0 = s0[0], mt1 = s1[0];
#pragma unroll
        for (int j = 1; j < 8; j++) { mt0 = fmaxf(mt0, s0[j]); mt1 = fmaxf(mt1, s1[j]); }
#pragma unroll
        for (int off = 1; off < 8; off <<= 1) {
            mt0 = fmaxf(mt0, __shfl_xor_sync(0xffffffffu, mt0, off));
            mt1 = fmaxf(mt1, __shfl_xor_sync(0xffffffffu, mt1, off));
        }
        float mn0 = fmaxf(mrow0, mt0);
        float mn1 = fmaxf(mrow1, mt1);
        float al0 = __expf(mrow0 - mn0);
        float al1 = __expf(mrow1 - mn1);
        mrow0 = mn0; mrow1 = mn1;

        float ls0 = 0.f, ls1 = 0.f;
#pragma unroll
        for (int j = 0; j < 8; j++) {
            float p0 = __expf(s0[j] - mn0);
            float p1 = __expf(s1[j] - mn1);
            Ps[r0 * 65 + tx * 8 + j] = p0;
            Ps[r1 * 65 + tx * 8 + j] = p1;
            ls0 += p0; ls1 += p1;
        }
#pragma unroll
        for (int off = 1; off < 8; off <<= 1) {
            ls0 += __shfl_xor_sync(0xffffffffu, ls0, off);
            ls1 += __shfl_xor_sync(0xffffffffu, ls1, off);
        }
        l0 = l0 * al0 + ls0;
        l1 = l1 * al1 + ls1;
#pragma unroll
        for (int j = 0; j < 8; j++) { O0[j] *= al0; O1[j] *= al1; }

        __syncthreads();
#pragma unroll
        for (int i = 0; i < 4; i++) {
            int id = tid + i * 256;
            int r = id >> 4;
            int c = (id & 15) << 2;
            float4 v = *(const float4*)&Vp[(size_t)(k0 + r) * DK + c];
            float* dst = &KVs[r * 65 + c];
            dst[0] = v.x; dst[1] = v.y; dst[2] = v.z; dst[3] = v.w;
        }
        __syncthreads();

#pragma unroll 4
        for (int k = 0; k < 64; k++) {
            float p0 = Ps[r0 * 65 + k];
            float p1 = Ps[r1 * 65 + k];
#pragma unroll
            for (int j = 0; j < 8; j++) {
                float v = KVs[k * 65 + tx * 8 + j];
                O0[j] += p0 * v;
                O1[j] += p1 * v;
            }
        }
    }

    const float inv0 = 1.f / l0;
    const float inv1 = 1.f / l1;
    const int h = bh & 15;
    const size_t base0 = ((size_t)(b * SEQ + q0 + r0)) * DMODEL + h * 64 + tx * 8;
    const size_t base1 = base0 + DMODEL;
#pragma unroll
    for (int j = 0; j < 8; j++) {
        g_ctx[base0 + j] = O0[j] * inv0;
        g_ctx[base1 + j] = O1[j] * inv1;
    }
}

// ---------------- launch ------------------------------------------------------
extern "C" void kernel_launch(void* const* d_in, const int* in_sizes, int n_in,
                              void* d_out, int out_size)
{
    const float* x  = (const float*)d_in[0];
    const int* mask = (const int*)d_in[1];
    const float* wq = (const float*)d_in[2];
    const float* bq = (const float*)d_in[3];
    const float* wk = (const float*)d_in[4];
    const float* bk = (const float*)d_in[5];
    const float* wv = (const float*)d_in[6];
    const float* bv = (const float*)d_in[7];
    const float* wo = (const float*)d_in[8];
    const float* bo = (const float*)d_in[9];

    float* d_xr;   cudaGetSymbolAddress((void**)&d_xr, g_xr);
    float* d_ctx;  cudaGetSymbolAddress((void**)&d_ctx, g_ctx);
    float* d_ctxr; cudaGetSymbolAddress((void**)&d_ctxr, g_ctxr);
    float* d_wqr;  cudaGetSymbolAddress((void**)&d_wqr, g_wqr);
    float* d_wkr;  cudaGetSymbolAddress((void**)&d_wkr, g_wkr);
    float* d_wvr;  cudaGetSymbolAddress((void**)&d_wvr, g_wvr);
    float* d_wor;  cudaGetSymbolAddress((void**)&d_wor, g_wor);

    const int nx4 = BATCH * SEQ * DMODEL / 4;   // 2M float4
    const int nw4 = DMODEL * DMODEL / 4;        // 256K float4
    round_tf32_kernel<<<(nx4 + 255) / 256, 256>>>(x, d_xr, nx4);
    round_tf32_kernel<<<(nw4 + 255) / 256, 256>>>(wq, d_wqr, nw4);
    round_tf32_kernel<<<(nw4 + 255) / 256, 256>>>(wk, d_wkr, nw4);
    round_tf32_kernel<<<(nw4 + 255) / 256, 256>>>(wv, d_wvr, nw4);
    round_tf32_kernel<<<(nw4 + 255) / 256, 256>>>(wo, d_wor, nw4);

    // 1) QKV projections
    cudaFuncSetAttribute(qkv_gemm_tf32,
                         cudaFuncAttributeMaxDynamicSharedMemorySize, SMEM_BYTES);
    dim3 g1(DMODEL / 256, (BATCH * SEQ) / 128, 3);
    qkv_gemm_tf32<<<g1, 256, SMEM_BYTES>>>(bq, bk, bv);

    // 2) flash attention
    const size_t shmem = 3 * 64 * 65 * sizeof(float);
    cudaFuncSetAttribute(flash_attn, cudaFuncAttributeMaxDynamicSharedMemorySize,
                         (int)shmem);
    flash_attn<<<dim3(SEQ / 64, BATCH * NHEADS), 256, shmem>>>(mask);

    // 3) round ctx, output projection
    round_tf32_kernel<<<(nx4 + 255) / 256, 256>>>(d_ctx, d_ctxr, nx4);
    cudaFuncSetAttribute(out_gemm_tf32,
                         cudaFuncAttributeMaxDynamicSharedMemorySize, SMEM_BYTES);
    dim3 g3(DMODEL / 256, (BATCH * SEQ) / 128);
    out_gemm_tf32<<<g3, 256, SMEM_BYTES>>>(bo, (float*)d_out);
}

// round 5
// speedup vs baseline: 5.4349x; 4.2618x over previous
#include <cuda_runtime.h>
#include <cuda_bf16.h>
#include <cstdint>

#define BATCH 4
#define SEQ   2048
#define DMODEL 1024
#define NHEADS 16
#define DK    64

// ---------------- scratch (static device globals; no allocation) ------------
__device__ float g_Q[BATCH * NHEADS * SEQ * DK];     // [B,H,S,Dk] (tf32-rounded)
__device__ float g_K[BATCH * NHEADS * SEQ * DK];
__device__ float g_V[BATCH * NHEADS * SEQ * DK];
__device__ float g_ctx[BATCH * SEQ * DMODEL];        // [B,S,D] (tf32-rounded)
__device__ float g_xr[BATCH * SEQ * DMODEL];
__device__ float g_wqr[DMODEL * DMODEL];
__device__ float g_wkr[DMODEL * DMODEL];
__device__ float g_wvr[DMODEL * DMODEL];
__device__ float g_wor[DMODEL * DMODEL];

// ---------------- tf32 rounding --------------------------------------------
__device__ __forceinline__ float round_tf32(float f) {
    uint32_t r;
    asm("cvt.rna.tf32.f32 %0, %1;" : "=r"(r) : "f"(f));
    return __uint_as_float(r);
}

__global__ void round_tf32_kernel(const float* __restrict__ src,
                                  float* __restrict__ dst, int n4)
{
    int i = blockIdx.x * blockDim.x + threadIdx.x;
    if (i < n4) {
        float4 v = ((const float4*)src)[i];
        v.x = round_tf32(v.x); v.y = round_tf32(v.y);
        v.z = round_tf32(v.z); v.w = round_tf32(v.w);
        ((float4*)dst)[i] = v;
    }
}

// ---------------- tf32 mma GEMM ----------------------------------------------
#define XS_F (128 * 36)
#define WS_F (32 * 264)
#define STAGE_F (XS_F + WS_F)
#define SMEM_BYTES (2 * STAGE_F * 4)

__device__ __forceinline__ void cp_async16(uint32_t smem, const void* gmem) {
    asm volatile("cp.async.ca.shared.global [%0], [%1], 16;\n"
                 :: "r"(smem), "l"(gmem));
}

// LAYOUT 0: out[m*1024+n] (plain).  LAYOUT 1: QKV scatter, tf32-rounded store.
template <int LAYOUT>
__device__ __forceinline__ void gemm_tf32_body(
    const float* __restrict__ X, const float* __restrict__ W,
    const float* __restrict__ bias, float* __restrict__ out)
{
    extern __shared__ float sm[];
    const uint32_t smem_u32 = (uint32_t)__cvta_generic_to_shared(sm);

    const int tid = threadIdx.x;
    const int m0 = blockIdx.y * 128;
    const int n0 = blockIdx.x * 256;
    const int warp = tid >> 5, lane = tid & 31;
    const int g = lane >> 2, q = lane & 3;
    const int wm = (warp >> 2) * 64;
    const int wn = (warp & 3) * 64;

    float acc[4][8][4];
#pragma unroll
    for (int i = 0; i < 4; i++)
#pragma unroll
        for (int j = 0; j < 8; j++)
#pragma unroll
            for (int c = 0; c < 4; c++) acc[i][j][c] = 0.f;

    const int xr_[4] = { (tid + 0) >> 3, (tid + 256) >> 3, (tid + 512) >> 3, (tid + 768) >> 3 };
    const int xc_ = (tid & 7) << 2;

    auto load_tiles = [&](int kt, int stage) {
        const uint32_t base = smem_u32 + stage * (STAGE_F * 4);
        const float* Xp = X + (size_t)m0 * DMODEL + kt * 32;
#pragma unroll
        for (int i = 0; i < 4; i++) {
            int r = xr_[i];
            cp_async16(base + (uint32_t)(r * 36 + xc_) * 4,
                       Xp + (size_t)r * DMODEL + xc_);
        }
        const float* Wp = W + (size_t)(kt * 32) * DMODEL + n0;
        const uint32_t wbase = base + XS_F * 4;
#pragma unroll
        for (int i = 0; i < 8; i++) {
            int id = tid + i * 256;
            int r = id >> 6;
            int c = (id & 63) << 2;
            cp_async16(wbase + (uint32_t)(r * 264 + c) * 4,
                       Wp + (size_t)r * DMODEL + c);
        }
    };

    auto compute = [&](int stage) {
        const float* Xs = sm + stage * STAGE_F;
        const float* Ws = Xs + XS_F;
#pragma unroll
        for (int ks4 = 0; ks4 < 4; ks4++) {
            const int ks = ks4 * 8;
            uint32_t a[4][4], b[8][2];
#pragma unroll
            for (int i = 0; i < 4; i++) {
                int row = wm + i * 16 + g;
                a[i][0] = __float_as_uint(Xs[row * 36 + ks + q]);
                a[i][1] = __float_as_uint(Xs[(row + 8) * 36 + ks + q]);
                a[i][2] = __float_as_uint(Xs[row * 36 + ks + q + 4]);
                a[i][3] = __float_as_uint(Xs[(row + 8) * 36 + ks + q + 4]);
            }
#pragma unroll
            for (int j = 0; j < 8; j++) {
                int col = wn + j * 8 + g;
                b[j][0] = __float_as_uint(Ws[(ks + q) * 264 + col]);
                b[j][1] = __float_as_uint(Ws[(ks + q + 4) * 264 + col]);
            }
#pragma unroll
            for (int i = 0; i < 4; i++)
#pragma unroll
                for (int j = 0; j < 8; j++) {
                    asm volatile(
                        "mma.sync.aligned.m16n8k8.row.col.f32.tf32.tf32.f32 "
                        "{%0,%1,%2,%3}, {%4,%5,%6,%7}, {%8,%9}, {%0,%1,%2,%3};\n"
                        : "+f"(acc[i][j][0]), "+f"(acc[i][j][1]),
                          "+f"(acc[i][j][2]), "+f"(acc[i][j][3])
                        : "r"(a[i][0]), "r"(a[i][1]), "r"(a[i][2]), "r"(a[i][3]),
                          "r"(b[j][0]), "r"(b[j][1]));
                }
        }
    };

    load_tiles(0, 0);
    asm volatile("cp.async.commit_group;\n" ::);

    for (int kt = 0; kt < DMODEL / 32; kt++) {
        const int cur = kt & 1;
        if (kt < DMODEL / 32 - 1) {
            load_tiles(kt + 1, cur ^ 1);
            asm volatile("cp.async.commit_group;\n" ::);
            asm volatile("cp.async.wait_group 1;\n" ::);
        } else {
            asm volatile("cp.async.wait_group 0;\n" ::);
        }
        __syncthreads();
        compute(cur);
        __syncthreads();
    }

#pragma unroll
    for (int i = 0; i < 4; i++) {
        const int mrow0 = m0 + wm + i * 16 + g;
        const int mrow1 = mrow0 + 8;
#pragma unroll
        for (int j = 0; j < 8; j++) {
            const int ncol = n0 + wn + j * 8 + q * 2;
            const float bi0 = bias[ncol], bi1 = bias[ncol + 1];
            float2 v0 = make_float2(acc[i][j][0] + bi0, acc[i][j][1] + bi1);
            float2 v1 = make_float2(acc[i][j][2] + bi0, acc[i][j][3] + bi1);
            if (LAYOUT == 0) {
                *(float2*)&out[(size_t)mrow0 * DMODEL + ncol] = v0;
                *(float2*)&out[(size_t)mrow1 * DMODEL + ncol] = v1;
            } else {
                v0.x = round_tf32(v0.x); v0.y = round_tf32(v0.y);
                v1.x = round_tf32(v1.x); v1.y = round_tf32(v1.y);
                const int h = ncol >> 6, dk = ncol & 63;
                {
                    const int b = mrow0 >> 11, s = mrow0 & (SEQ - 1);
                    *(float2*)&out[(((size_t)(b * NHEADS + h) * SEQ + s) << 6) + dk] = v0;
                }
                {
                    const int b = mrow1 >> 11, s = mrow1 & (SEQ - 1);
                    *(float2*)&out[(((size_t)(b * NHEADS + h) * SEQ + s) << 6) + dk] = v1;
                }
            }
        }
    }
}

__global__ __launch_bounds__(256, 1) void qkv_gemm_tf32(
    const float* __restrict__ bq, const float* __restrict__ bk,
    const float* __restrict__ bv)
{
    const float* W;
    const float* bias;
    float* out;
    if (blockIdx.z == 0)      { W = g_wqr; bias = bq; out = g_Q; }
    else if (blockIdx.z == 1) { W = g_wkr; bias = bk; out = g_K; }
    else                      { W = g_wvr; bias = bv; out = g_V; }
    gemm_tf32_body<1>(g_xr, W, bias, out);
}

__global__ __launch_bounds__(256, 1) void out_gemm_tf32(
    const float* __restrict__ bo, float* __restrict__ out)
{
    gemm_tf32_body<0>(g_ctx, g_wor, bo, out);
}

// ---------------- flash attention with tf32 mma ------------------------------
// CTA: 128 queries x full seq, key tiles of 64, 8 warps x 16 q-rows.
// smem strides 68: all fragment loads map to banks 4g+q / 4q+g (conflict-free).
#define STQ 68
#define QS_F   (128 * STQ)            // 8704
#define KS_F   (64 * STQ)             // 4352 per stage
#define ATT_SMEM_BYTES ((QS_F + 4 * KS_F + QS_F) * 4 + SEQ * 4)  // Q,K2,V2,P + mask

__global__ __launch_bounds__(256, 1) void flash_attn_tf32(const int* __restrict__ mask)
{
    extern __shared__ float smf[];
    float* Qs = smf;                       // 128x68
    float* Ks = smf + QS_F;                // 2 stages x 64x68
    float* Vs = Ks + 2 * KS_F;             // 2 stages x 64x68
    float* Ps = Vs + 2 * KS_F;             // 128x68 (warp-private rows)
    int*   Ms = (int*)(Ps + QS_F);         // 2048 mask ints

    const uint32_t smem_u32 = (uint32_t)__cvta_generic_to_shared(smf);
    const uint32_t Ks_u = smem_u32 + QS_F * 4;
    const uint32_t Vs_u = Ks_u + 2 * KS_F * 4;

    const int bh = blockIdx.y;
    const int b  = bh >> 4;
    const int h  = bh & 15;
    const int q0 = blockIdx.x * 128;
    const int tid = threadIdx.x;
    const int warp = tid >> 5, lane = tid & 31;
    const int g = lane >> 2, q = lane & 3;
    const int wq0 = warp * 16;

    const float* Qp = g_Q + (size_t)bh * SEQ * DK + (size_t)q0 * DK;
    const float* Kp = g_K + (size_t)bh * SEQ * DK;
    const float* Vp = g_V + (size_t)bh * SEQ * DK;

    // load Q tile (128x64) and mask row (2048)
#pragma unroll
    for (int i = 0; i < 8; i++) {
        int id = tid + i * 256;
        int r = id >> 4, c = (id & 15) << 2;
        *(float4*)&Qs[r * STQ + c] = *(const float4*)&Qp[(size_t)r * DK + c];
    }
    const int* mbase = mask + b * SEQ;
#pragma unroll
    for (int i = 0; i < 8; i++) Ms[tid + i * 256] = mbase[tid + i * 256];

    auto issue_kv = [&](int kt) {
        const int stage = kt & 1;
        const float* Kpt = Kp + (size_t)kt * 64 * DK;
        const float* Vpt = Vp + (size_t)kt * 64 * DK;
        const uint32_t kb = Ks_u + stage * KS_F * 4;
        const uint32_t vb = Vs_u + stage * KS_F * 4;
#pragma unroll
        for (int i = 0; i < 4; i++) {
            int id = tid + i * 256;
            int r = id >> 4, c = (id & 15) << 2;
            cp_async16(kb + (uint32_t)(r * STQ + c) * 4, Kpt + (size_t)r * DK + c);
            cp_async16(vb + (uint32_t)(r * STQ + c) * 4, Vpt + (size_t)r * DK + c);
        }
    };

    issue_kv(0); asm volatile("cp.async.commit_group;\n" ::);
    issue_kv(1); asm volatile("cp.async.commit_group;\n" ::);

    float m0 = -1e30f, m1 = -1e30f, l0 = 0.f, l1 = 0.f;
    float o[8][4];
#pragma unroll
    for (int j = 0; j < 8; j++)
#pragma unroll
        for (int c = 0; c < 4; c++) o[j][c] = 0.f;

    const int NKT = SEQ / 64;
    for (int kt = 0; kt < NKT; kt++) {
        if (kt < NKT - 1) asm volatile("cp.async.wait_group 1;\n" ::);
        else              asm volatile("cp.async.wait_group 0;\n" ::);
        __syncthreads();

        const float* Kt = Ks + (kt & 1) * KS_F;
        const float* Vt = Vs + (kt & 1) * KS_F;

        // ---- S = Q @ K^T  (16x64 per warp) ----
        float s[8][4];
#pragma unroll
        for (int j = 0; j < 8; j++)
#pragma unroll
            for (int c = 0; c < 4; c++) s[j][c] = 0.f;

#pragma unroll
        for (int ks = 0; ks < 8; ks++) {
            const int kc = ks * 8;
            uint32_t a0 = __float_as_uint(Qs[(wq0 + g) * STQ + kc + q]);
            uint32_t a1 = __float_as_uint(Qs[(wq0 + g + 8) * STQ + kc + q]);
            uint32_t a2 = __float_as_uint(Qs[(wq0 + g) * STQ + kc + q + 4]);
            uint32_t a3 = __float_as_uint(Qs[(wq0 + g + 8) * STQ + kc + q + 4]);
#pragma unroll
            for (int nt = 0; nt < 8; nt++) {
                uint32_t b0 = __float_as_uint(Kt[(nt * 8 + g) * STQ + kc + q]);
                uint32_t b1 = __float_as_uint(Kt[(nt * 8 + g) * STQ + kc + q + 4]);
                asm volatile(
                    "mma.sync.aligned.m16n8k8.row.col.f32.tf32.tf32.f32 "
                    "{%0,%1,%2,%3}, {%4,%5,%6,%7}, {%8,%9}, {%0,%1,%2,%3};\n"
                    : "+f"(s[nt][0]), "+f"(s[nt][1]), "+f"(s[nt][2]), "+f"(s[nt][3])
                    : "r"(a0), "r"(a1), "r"(a2), "r"(a3), "r"(b0), "r"(b1));
            }
        }

        // ---- mask + scale ----
        const int kbase = kt * 64;
#pragma unroll
        for (int nt = 0; nt < 8; nt++) {
            const int mv0 = Ms[kbase + nt * 8 + 2 * q];
            const int mv1 = Ms[kbase + nt * 8 + 2 * q + 1];
            s[nt][0] = mv0 ? s[nt][0] * 0.125f : -1e9f;
            s[nt][1] = mv1 ? s[nt][1] * 0.125f : -1e9f;
            s[nt][2] = mv0 ? s[nt][2] * 0.125f : -1e9f;
            s[nt][3] = mv1 ? s[nt][3] * 0.125f : -1e9f;
        }

        // ---- online softmax (rows r0 = wq0+g, r1 = r0+8) ----
        float mt0 = s[0][0], mt1 = s[0][2];
#pragma unroll
        for (int nt = 0; nt < 8; nt++) {
            mt0 = fmaxf(mt0, fmaxf(s[nt][0], s[nt][1]));
            mt1 = fmaxf(mt1, fmaxf(s[nt][2], s[nt][3]));
        }
        mt0 = fmaxf(mt0, __shfl_xor_sync(0xffffffffu, mt0, 1));
        mt0 = fmaxf(mt0, __shfl_xor_sync(0xffffffffu, mt0, 2));
        mt1 = fmaxf(mt1, __shfl_xor_sync(0xffffffffu, mt1, 1));
        mt1 = fmaxf(mt1, __shfl_xor_sync(0xffffffffu, mt1, 2));

        const float nm0 = fmaxf(m0, mt0);
        const float nm1 = fmaxf(m1, mt1);
        const float al0 = __expf(m0 - nm0);
        const float al1 = __expf(m1 - nm1);
        m0 = nm0; m1 = nm1;

        float ls0 = 0.f, ls1 = 0.f;
#pragma unroll
        for (int nt = 0; nt < 8; nt++) {
            float p00 = __expf(s[nt][0] - nm0);
            float p01 = __expf(s[nt][1] - nm0);
            float p10 = __expf(s[nt][2] - nm1);
            float p11 = __expf(s[nt][3] - nm1);
            ls0 += p00 + p01;
            ls1 += p10 + p11;
            float2 v0 = make_float2(round_tf32(p00), round_tf32(p01));
            float2 v1 = make_float2(round_tf32(p10), round_tf32(p11));
            *(float2*)&Ps[(wq0 + g) * STQ + nt * 8 + 2 * q] = v0;
            *(float2*)&Ps[(wq0 + g + 8) * STQ + nt * 8 + 2 * q] = v1;
        }
        ls0 += __shfl_xor_sync(0xffffffffu, ls0, 1);
        ls0 += __shfl_xor_sync(0xffffffffu, ls0, 2);
        ls1 += __shfl_xor_sync(0xffffffffu, ls1, 1);
        ls1 += __shfl_xor_sync(0xffffffffu, ls1, 2);
        l0 = l0 * al0 + ls0;
        l1 = l1 * al1 + ls1;

#pragma unroll
        for (int nt = 0; nt < 8; nt++) {
            o[nt][0] *= al0; o[nt][1] *= al0;
            o[nt][2] *= al1; o[nt][3] *= al1;
        }

        __syncwarp();   // Ps visibility (warp-private rows)

        // ---- O += P @ V  (16x64 per warp) ----
#pragma unroll
        for (int ks = 0; ks < 8; ks++) {
            const int kc = ks * 8;
            uint32_t a0 = __float_as_uint(Ps[(wq0 + g) * STQ + kc + q]);
            uint32_t a1 = __float_as_uint(Ps[(wq0 + g + 8) * STQ + kc + q]);
            uint32_t a2 = __float_as_uint(Ps[(wq0 + g) * STQ + kc + q + 4]);
            uint32_t a3 = __float_as_uint(Ps[(wq0 + g + 8) * STQ + kc + q + 4]);
#pragma unroll
            for (int nt = 0; nt < 8; nt++) {
                uint32_t b0 = __float_as_uint(Vt[(kc + q) * STQ + nt * 8 + g]);
                uint32_t b1 = __float_as_uint(Vt[(kc + q + 4) * STQ + nt * 8 + g]);
                asm volatile(
                    "mma.sync.aligned.m16n8k8.row.col.f32.tf32.tf32.f32 "
                    "{%0,%1,%2,%3}, {%4,%5,%6,%7}, {%8,%9}, {%0,%1,%2,%3};\n"
                    : "+f"(o[nt][0]), "+f"(o[nt][1]), "+f"(o[nt][2]), "+f"(o[nt][3])
                    : "r"(a0), "r"(a1), "r"(a2), "r"(a3), "r"(b0), "r"(b1));
            }
        }

        __syncthreads();  // done reading this stage before it is re-filled

        if (kt + 2 < NKT) {
            issue_kv(kt + 2);
            asm volatile("cp.async.commit_group;\n" ::);
        }
    }

    // ---- epilogue: normalize, round to tf32, write ctx [B,S,D] ----
    const float inv0 = 1.f / l0;
    const float inv1 = 1.f / l1;
    const int row0 = q0 + wq0 + g;
    const int row1 = row0 + 8;
    float* out0 = g_ctx + (size_t)(b * SEQ + row0) * DMODEL + h * 64;
    float* out1 = g_ctx + (size_t)(b * SEQ + row1) * DMODEL + h * 64;
#pragma unroll
    for (int nt = 0; nt < 8; nt++) {
        const int c = nt * 8 + 2 * q;
        float2 v0 = make_float2(round_tf32(o[nt][0] * inv0), round_tf32(o[nt][1] * inv0));
        float2 v1 = make_float2(round_tf32(o[nt][2] * inv1), round_tf32(o[nt][3] * inv1));
        *(float2*)&out0[c] = v0;
        *(float2*)&out1[c] = v1;
    }
}

// ---------------- launch ------------------------------------------------------
extern "C" void kernel_launch(void* const* d_in, const int* in_sizes, int n_in,
                              void* d_out, int out_size)
{
    const float* x  = (const float*)d_in[0];
    const int* mask = (const int*)d_in[1];
    const float* wq = (const float*)d_in[2];
    const float* bq = (const float*)d_in[3];
    const float* wk = (const float*)d_in[4];
    const float* bk = (const float*)d_in[5];
    const float* wv = (const float*)d_in[6];
    const float* bv = (const float*)d_in[7];
    const float* wo = (const float*)d_in[8];
    const float* bo = (const float*)d_in[9];

    float* d_xr;   cudaGetSymbolAddress((void**)&d_xr, g_xr);
    float* d_wqr;  cudaGetSymbolAddress((void**)&d_wqr, g_wqr);
    float* d_wkr;  cudaGetSymbolAddress((void**)&d_wkr, g_wkr);
    float* d_wvr;  cudaGetSymbolAddress((void**)&d_wvr, g_wvr);
    float* d_wor;  cudaGetSymbolAddress((void**)&d_wor, g_wor);

    const int nx4 = BATCH * SEQ * DMODEL / 4;
    const int nw4 = DMODEL * DMODEL / 4;
    round_tf32_kernel<<<(nx4 + 255) / 256, 256>>>(x, d_xr, nx4);
    round_tf32_kernel<<<(nw4 + 255) / 256, 256>>>(wq, d_wqr, nw4);
    round_tf32_kernel<<<(nw4 + 255) / 256, 256>>>(wk, d_wkr, nw4);
    round_tf32_kernel<<<(nw4 + 255) / 256, 256>>>(wv, d_wvr, nw4);
    round_tf32_kernel<<<(nw4 + 255) / 256, 256>>>(wo, d_wor, nw4);

    // 1) QKV projections (epilogue rounds Q/K/V to tf32)
    cudaFuncSetAttribute(qkv_gemm_tf32,
                         cudaFuncAttributeMaxDynamicSharedMemorySize, SMEM_BYTES);
    dim3 g1(DMODEL / 256, (BATCH * SEQ) / 128, 3);
    qkv_gemm_tf32<<<g1, 256, SMEM_BYTES>>>(bq, bk, bv);

    // 2) flash attention (tf32 mma)
    cudaFuncSetAttribute(flash_attn_tf32,
                         cudaFuncAttributeMaxDynamicSharedMemorySize, ATT_SMEM_BYTES);
    flash_attn_tf32<<<dim3(SEQ / 128, BATCH * NHEADS), 256, ATT_SMEM_BYTES>>>(mask);

    // 3) output projection (reads tf32-rounded ctx directly)
    cudaFuncSetAttribute(out_gemm_tf32,
                         cudaFuncAttributeMaxDynamicSharedMemorySize, SMEM_BYTES);
    dim3 g3(DMODEL / 256, (BATCH * SEQ) / 128);
    out_gemm_tf32<<<g3, 256, SMEM_BYTES>>>(bo, (float*)d_out);
}

// round 8
// speedup vs baseline: 11.1651x; 2.0543x over previous
#include <cuda_runtime.h>
#include <cuda_fp16.h>
#include <cstdint>

#define BATCH 4
#define SEQ   2048
#define DMODEL 1024
#define NHEADS 16
#define DK    64

// ---------------- scratch (static device globals; no allocation) ------------
__device__ __half g_Qh[BATCH * NHEADS * SEQ * DK];    // [B,H,S,Dk] fp16
__device__ __half g_Kh[BATCH * NHEADS * SEQ * DK];    // [B,H,S,Dk] fp16
__device__ __half g_Vh[BATCH * NHEADS * DK * SEQ];    // [B,H,Dk,S] fp16 (transposed)
__device__ __half g_ctxh[BATCH * SEQ * DMODEL];       // [B,S,D] fp16
__device__ __half g_xh[BATCH * SEQ * DMODEL];         // x fp16
__device__ __half g_wqt[DMODEL * DMODEL];             // [N,K] fp16 (transposed)
__device__ __half g_wkt[DMODEL * DMODEL];
__device__ __half g_wvt[DMODEL * DMODEL];
__device__ __half g_wot[DMODEL * DMODEL];

// ---------------- helpers ----------------------------------------------------
__device__ __forceinline__ void cp_async16(uint32_t smem, const void* gmem) {
    asm volatile("cp.async.ca.shared.global [%0], [%1], 16;\n"
                 :: "r"(smem), "l"(gmem));
}
#define CP_COMMIT()  asm volatile("cp.async.commit_group;\n" ::)
#define CP_WAIT(n)   asm volatile("cp.async.wait_group %0;\n" :: "n"(n))

#define MMA_F16(d0,d1,d2,d3,a0,a1,a2,a3,b0,b1)                                  \
    asm volatile(                                                               \
        "mma.sync.aligned.m16n8k16.row.col.f32.f16.f16.f32 "                    \
        "{%0,%1,%2,%3}, {%4,%5,%6,%7}, {%8,%9}, {%0,%1,%2,%3};\n"               \
        : "+f"(d0), "+f"(d1), "+f"(d2), "+f"(d3)                                \
        : "r"(a0), "r"(a1), "r"(a2), "r"(a3), "r"(b0), "r"(b1))

// ---------------- prep kernels -----------------------------------------------
// f32 -> f16 (rn), vectorized
__global__ void cvt_f16_kernel(const float* __restrict__ src,
                               __half* __restrict__ dst, int n4)
{
    int i = blockIdx.x * blockDim.x + threadIdx.x;
    if (i < n4) {
        float4 v = ((const float4*)src)[i];
        __half2 h0 = __floats2half2_rn(v.x, v.y);
        __half2 h1 = __floats2half2_rn(v.z, v.w);
        uint2 u;
        u.x = *(uint32_t*)&h0;
        u.y = *(uint32_t*)&h1;
        ((uint2*)dst)[i] = u;
    }
}

// W [K,N] f32 row-major -> Wt [N,K] f16 row-major
__global__ void cvt_transpose_kernel(const float* __restrict__ src,
                                     __half* __restrict__ dst)
{
    __shared__ float t[32][33];
    const int bx = blockIdx.x * 32;   // n
    const int by = blockIdx.y * 32;   // k
    const int tx = threadIdx.x & 31, ty = threadIdx.x >> 5;  // ty 0..7
#pragma unroll
    for (int i = 0; i < 4; i++)
        t[ty + i * 8][tx] = src[(size_t)(by + ty + i * 8) * DMODEL + bx + tx];
    __syncthreads();
#pragma unroll
    for (int i = 0; i < 4; i++)
        dst[(size_t)(bx + ty + i * 8) * DMODEL + by + tx] =
            __float2half_rn(t[tx][ty + i * 8]);
}

// ---------------- fp16 mma GEMM ----------------------------------------------
// C[8192,1024] = X[8192,1024] @ Wt[1024,1024]^T + bias
// CTA tile 128x256, k-block 64. 8 warps (2m x 4n), warp tile 64x64.
// smem stride 72 halves (144B) -> all fragment loads bank-conflict-free.
#define GST 72
#define GA_H  (128 * GST)              // 9216 halves per A stage
#define GB_H  (256 * GST)              // 18432 halves per B stage
#define GSMEM ((2 * GA_H + 2 * GB_H) * 2)   // 110592 bytes

// LAYOUT 0: fp32 out[m*1024+n].  LAYOUT 1: Q/K fp16 scatter [B,H,S,dk].
// LAYOUT 2: V fp16 transposed scatter [B,H,dk,S].
template <int LAYOUT>
__device__ __forceinline__ void gemm_f16_body(
    const __half* __restrict__ X, const __half* __restrict__ Wt,
    const float* __restrict__ bias, void* __restrict__ outv)
{
    extern __shared__ __half gsmh[];
    const uint32_t smem_u32 = (uint32_t)__cvta_generic_to_shared(gsmh);

    const int tid = threadIdx.x;
    const int m0 = blockIdx.y * 128;
    const int n0 = blockIdx.x * 256;
    const int warp = tid >> 5, lane = tid & 31;
    const int g = lane >> 2, q = lane & 3;
    const int wm = (warp >> 2) * 64;
    const int wn = (warp & 3) * 64;

    float acc[4][8][4];
#pragma unroll
    for (int i = 0; i < 4; i++)
#pragma unroll
        for (int j = 0; j < 8; j++)
#pragma unroll
            for (int c = 0; c < 4; c++) acc[i][j][c] = 0.f;

    auto load_chunk = [&](int kt, int stage) {
        const __half* Xp = X + (size_t)m0 * DMODEL + kt * 64;
        const uint32_t ab = smem_u32 + stage * (GA_H * 2);
#pragma unroll
        for (int i = 0; i < 4; i++) {            // 1024 cp16
            int id = tid + i * 256;
            int r = id >> 3, c = id & 7;
            cp_async16(ab + (uint32_t)(r * (GST * 2) + c * 16),
                       Xp + (size_t)r * DMODEL + c * 8);
        }
        const __half* Bp = Wt + (size_t)n0 * DMODEL + kt * 64;
        const uint32_t bb = smem_u32 + 2 * GA_H * 2 + stage * (GB_H * 2);
#pragma unroll
        for (int i = 0; i < 8; i++) {            // 2048 cp16
            int id = tid + i * 256;
            int r = id >> 3, c = id & 7;
            cp_async16(bb + (uint32_t)(r * (GST * 2) + c * 16),
                       Bp + (size_t)r * DMODEL + c * 8);
        }
    };

    auto compute = [&](int stage) {
        const __half* Xs = gsmh + stage * GA_H;
        const __half* Ws = gsmh + 2 * GA_H + stage * GB_H;
#pragma unroll
        for (int ks = 0; ks < 4; ks++) {
            const int kc = ks * 16 + 2 * q;
            uint32_t a[4][4], b[8][2];
#pragma unroll
            for (int i = 0; i < 4; i++) {
                const int row = wm + i * 16 + g;
                a[i][0] = *(const uint32_t*)&Xs[row * GST + kc];
                a[i][1] = *(const uint32_t*)&Xs[(row + 8) * GST + kc];
                a[i][2] = *(const uint32_t*)&Xs[row * GST + kc + 8];
                a[i][3] = *(const uint32_t*)&Xs[(row + 8) * GST + kc + 8];
            }
#pragma unroll
            for (int j = 0; j < 8; j++) {
                const int col = wn + j * 8 + g;
                b[j][0] = *(const uint32_t*)&Ws[col * GST + kc];
                b[j][1] = *(const uint32_t*)&Ws[col * GST + kc + 8];
            }
#pragma unroll
            for (int i = 0; i < 4; i++)
#pragma unroll
                for (int j = 0; j < 8; j++)
                    MMA_F16(acc[i][j][0], acc[i][j][1], acc[i][j][2], acc[i][j][3],
                            a[i][0], a[i][1], a[i][2], a[i][3], b[j][0], b[j][1]);
        }
    };

    load_chunk(0, 0);
    CP_COMMIT();

    const int NKT = DMODEL / 64;   // 16
    for (int kt = 0; kt < NKT; kt++) {
        const int cur = kt & 1;
        if (kt < NKT - 1) {
            load_chunk(kt + 1, cur ^ 1);
            CP_COMMIT();
            CP_WAIT(1);
        } else {
            CP_WAIT(0);
        }
        __syncthreads();
        compute(cur);
        __syncthreads();
    }

    // epilogue
#pragma unroll
    for (int i = 0; i < 4; i++) {
        const int mrow0 = m0 + wm + i * 16 + g;
        const int mrow1 = mrow0 + 8;
        const int b0i = mrow0 >> 11, s0i = mrow0 & (SEQ - 1);
        const int b1i = mrow1 >> 11, s1i = mrow1 & (SEQ - 1);
#pragma unroll
        for (int j = 0; j < 8; j++) {
            const int ncol = n0 + wn + j * 8 + q * 2;
            const float bi0 = bias[ncol], bi1 = bias[ncol + 1];
            const float c0 = acc[i][j][0] + bi0, c1 = acc[i][j][1] + bi1;
            const float c2 = acc[i][j][2] + bi0, c3 = acc[i][j][3] + bi1;
            if (LAYOUT == 0) {
                float* out = (float*)outv;
                *(float2*)&out[(size_t)mrow0 * DMODEL + ncol] = make_float2(c0, c1);
                *(float2*)&out[(size_t)mrow1 * DMODEL + ncol] = make_float2(c2, c3);
            } else if (LAYOUT == 1) {
                __half* out = (__half*)outv;
                const int h = ncol >> 6, dk = ncol & 63;
                __half2 v0 = __floats2half2_rn(c0, c1);
                __half2 v1 = __floats2half2_rn(c2, c3);
                *(__half2*)&out[(((size_t)(b0i * NHEADS + h) * SEQ + s0i) << 6) + dk] = v0;
                *(__half2*)&out[(((size_t)(b1i * NHEADS + h) * SEQ + s1i) << 6) + dk] = v1;
            } else {
                __half* out = (__half*)outv;
                const int h = ncol >> 6, dk = ncol & 63;
                const size_t base = ((size_t)(b0i * NHEADS + h) * DK + dk) * SEQ;
                out[base + s0i]       = __float2half_rn(c0);
                out[base + SEQ + s0i] = __float2half_rn(c1);
                const size_t base1 = ((size_t)(b1i * NHEADS + h) * DK + dk) * SEQ;
                out[base1 + s1i]       = __float2half_rn(c2);
                out[base1 + SEQ + s1i] = __float2half_rn(c3);
            }
        }
    }
}

__global__ __launch_bounds__(256, 1) void qk_gemm_f16(
    const float* __restrict__ bq, const float* __restrict__ bk)
{
    if (blockIdx.z == 0) gemm_f16_body<1>(g_xh, g_wqt, bq, g_Qh);
    else                 gemm_f16_body<1>(g_xh, g_wkt, bk, g_Kh);
}

__global__ __launch_bounds__(256, 1) void v_gemm_f16(const float* __restrict__ bv)
{
    gemm_f16_body<2>(g_xh, g_wvt, bv, g_Vh);
}

__global__ __launch_bounds__(256, 1) void out_gemm_f16(
    const float* __restrict__ bo, float* __restrict__ out)
{
    gemm_f16_body<0>(g_ctxh, g_wot, bo, out);
}

// ---------------- flash attention, fp16 mma ----------------------------------
// CTA: 128 queries, key tiles of 64, 8 warps x 16 q-rows, m16n8k16.
#define AST 72
#define AQ_H (128 * AST)     // Qs
#define AK_H (64 * AST)      // per K/V stage
#define AP_H (128 * AST)     // Ps
// halves: Qs + 2*Ks + 2*Vs + Ps = 9216+9216+9216+9216 = 36864 -> 73728 B + mask 8192
#define ATT_SMEM_BYTES (36864 * 2 + SEQ * 4)

__global__ __launch_bounds__(256, 2) void flash_attn_f16(const int* __restrict__ mask)
{
    extern __shared__ __half smh[];
    __half* Qs = smh;                      // 128 x 72
    __half* Ks = smh + AQ_H;               // 2 x 64 x 72
    __half* Vs = Ks + 2 * AK_H;            // 2 x 64 x 72 ([dk][key])
    __half* Ps = Vs + 2 * AK_H;            // 128 x 72
    int*    Ms = (int*)(Ps + AP_H);        // 2048 ints

    const uint32_t smem_u32 = (uint32_t)__cvta_generic_to_shared(smh);
    const uint32_t Qs_u = smem_u32;
    const uint32_t Ks_u = smem_u32 + AQ_H * 2;
    const uint32_t Vs_u = Ks_u + 2 * AK_H * 2;

    const int bh = blockIdx.y;
    const int b  = bh >> 4;
    const int h  = bh & 15;
    const int q0 = blockIdx.x * 128;
    const int tid = threadIdx.x;
    const int warp = tid >> 5, lane = tid & 31;
    const int g = lane >> 2, q = lane & 3;
    const int wq0 = warp * 16;

    const __half* Qp = g_Qh + (size_t)bh * SEQ * DK + (size_t)q0 * DK;
    const __half* Kp = g_Kh + (size_t)bh * SEQ * DK;
    const __half* Vp = g_Vh + (size_t)bh * DK * SEQ;   // [dk][S]

    // Q tile: 128 rows x 64 halves = 1024 cp16
#pragma unroll
    for (int i = 0; i < 4; i++) {
        int id = tid + i * 256;
        int r = id >> 3, c = id & 7;
        cp_async16(Qs_u + (uint32_t)(r * (AST * 2) + c * 16),
                   Qp + (size_t)r * DK + c * 8);
    }
    const int* mbase = mask + b * SEQ;
#pragma unroll
    for (int i = 0; i < 8; i++) Ms[tid + i * 256] = mbase[tid + i * 256];

    auto issue_kv = [&](int kt) {
        const int stage = kt & 1;
        const __half* Kpt = Kp + (size_t)kt * 64 * DK;
        const __half* Vpt = Vp + (size_t)kt * 64;      // column offset in [dk][S]
        const uint32_t kb = Ks_u + stage * (AK_H * 2);
        const uint32_t vb = Vs_u + stage * (AK_H * 2);
#pragma unroll
        for (int i = 0; i < 2; i++) {     // K: 512 cp16
            int id = tid + i * 256;
            int r = id >> 3, c = id & 7;
            cp_async16(kb + (uint32_t)(r * (AST * 2) + c * 16),
                       Kpt + (size_t)r * DK + c * 8);
        }
#pragma unroll
        for (int i = 0; i < 2; i++) {     // V: 512 cp16 ([dk] rows, stride SEQ)
            int id = tid + i * 256;
            int r = id >> 3, c = id & 7;
            cp_async16(vb + (uint32_t)(r * (AST * 2) + c * 16),
                       Vpt + (size_t)r * SEQ + c * 8);
        }
    };

    issue_kv(0); CP_COMMIT();
    issue_kv(1); CP_COMMIT();

    float m0 = -1e30f, m1 = -1e30f, l0 = 0.f, l1 = 0.f;
    float o[8][4];
#pragma unroll
    for (int j = 0; j < 8; j++)
#pragma unroll
        for (int c = 0; c < 4; c++) o[j][c] = 0.f;

    const int NKT = SEQ / 64;
    for (int kt = 0; kt < NKT; kt++) {
        if (kt < NKT - 1) CP_WAIT(1); else CP_WAIT(0);
        __syncthreads();

        const __half* Kt = Ks + (kt & 1) * AK_H;
        const __half* Vt = Vs + (kt & 1) * AK_H;

        // ---- S = Q @ K^T (16x64 per warp): 4 ksteps x 8 ntiles ----
        float s[8][4];
#pragma unroll
        for (int j = 0; j < 8; j++)
#pragma unroll
            for (int c = 0; c < 4; c++) s[j][c] = 0.f;

#pragma unroll
        for (int ks = 0; ks < 4; ks++) {
            const int kc = ks * 16 + 2 * q;
            uint32_t a0 = *(const uint32_t*)&Qs[(wq0 + g) * AST + kc];
            uint32_t a1 = *(const uint32_t*)&Qs[(wq0 + g + 8) * AST + kc];
            uint32_t a2 = *(const uint32_t*)&Qs[(wq0 + g) * AST + kc + 8];
            uint32_t a3 = *(const uint32_t*)&Qs[(wq0 + g + 8) * AST + kc + 8];
#pragma unroll
            for (int nt = 0; nt < 8; nt++) {
                uint32_t b0 = *(const uint32_t*)&Kt[(nt * 8 + g) * AST + kc];
                uint32_t b1 = *(const uint32_t*)&Kt[(nt * 8 + g) * AST + kc + 8];
                MMA_F16(s[nt][0], s[nt][1], s[nt][2], s[nt][3],
                        a0, a1, a2, a3, b0, b1);
            }
        }

        // ---- mask + scale ----
        const int kbase = kt * 64;
#pragma unroll
        for (int nt = 0; nt < 8; nt++) {
            const int mv0 = Ms[kbase + nt * 8 + 2 * q];
            const int mv1 = Ms[kbase + nt * 8 + 2 * q + 1];
            s[nt][0] = mv0 ? s[nt][0] * 0.125f : -1e9f;
            s[nt][1] = mv1 ? s[nt][1] * 0.125f : -1e9f;
            s[nt][2] = mv0 ? s[nt][2] * 0.125f : -1e9f;
            s[nt][3] = mv1 ? s[nt][3] * 0.125f : -1e9f;
        }

        // ---- online softmax (rows wq0+g, wq0+g+8) ----
        float mt0 = s[0][0], mt1 = s[0][2];
#pragma unroll
        for (int nt = 0; nt < 8; nt++) {
            mt0 = fmaxf(mt0, fmaxf(s[nt][0], s[nt][1]));
            mt1 = fmaxf(mt1, fmaxf(s[nt][2], s[nt][3]));
        }
        mt0 = fmaxf(mt0, __shfl_xor_sync(0xffffffffu, mt0, 1));
        mt0 = fmaxf(mt0, __shfl_xor_sync(0xffffffffu, mt0, 2));
        mt1 = fmaxf(mt1, __shfl_xor_sync(0xffffffffu, mt1, 1));
        mt1 = fmaxf(mt1, __shfl_xor_sync(0xffffffffu, mt1, 2));

        const float nm0 = fmaxf(m0, mt0);
        const float nm1 = fmaxf(m1, mt1);
        const float al0 = __expf(m0 - nm0);
        const float al1 = __expf(m1 - nm1);
        m0 = nm0; m1 = nm1;

        float ls0 = 0.f, ls1 = 0.f;
#pragma unroll
        for (int nt = 0; nt < 8; nt++) {
            float p00 = __expf(s[nt][0] - nm0);
            float p01 = __expf(s[nt][1] - nm0);
            float p10 = __expf(s[nt][2] - nm1);
            float p11 = __expf(s[nt][3] - nm1);
            ls0 += p00 + p01;
            ls1 += p10 + p11;
            __half2 h0 = __floats2half2_rn(p00, p01);
            __half2 h1 = __floats2half2_rn(p10, p11);
            *(__half2*)&Ps[(wq0 + g) * AST + nt * 8 + 2 * q] = h0;
            *(__half2*)&Ps[(wq0 + g + 8) * AST + nt * 8 + 2 * q] = h1;
        }
        ls0 += __shfl_xor_sync(0xffffffffu, ls0, 1);
        ls0 += __shfl_xor_sync(0xffffffffu, ls0, 2);
        ls1 += __shfl_xor_sync(0xffffffffu, ls1, 1);
        ls1 += __shfl_xor_sync(0xffffffffu, ls1, 2);
        l0 = l0 * al0 + ls0;
        l1 = l1 * al1 + ls1;

#pragma unroll
        for (int nt = 0; nt < 8; nt++) {
            o[nt][0] *= al0; o[nt][1] *= al0;
            o[nt][2] *= al1; o[nt][3] *= al1;
        }

        __syncwarp();   // Ps rows are warp-private

        // ---- O += P @ V  (B = Vs[dk][key], n=dk, k=key) ----
#pragma unroll
        for (int ks = 0; ks < 4; ks++) {
            const int kc = ks * 16 + 2 * q;
            uint32_t a0 = *(const uint32_t*)&Ps[(wq0 + g) * AST + kc];
            uint32_t a1 = *(const uint32_t*)&Ps[(wq0 + g + 8) * AST + kc];
            uint32_t a2 = *(const uint32_t*)&Ps[(wq0 + g) * AST + kc + 8];
            uint32_t a3 = *(const uint32_t*)&Ps[(wq0 + g + 8) * AST + kc + 8];
#pragma unroll
            for (int nt = 0; nt < 8; nt++) {
                uint32_t b0 = *(const uint32_t*)&Vt[(nt * 8 + g) * AST + kc];
                uint32_t b1 = *(const uint32_t*)&Vt[(nt * 8 + g) * AST + kc + 8];
                MMA_F16(o[nt][0], o[nt][1], o[nt][2], o[nt][3],
                        a0, a1, a2, a3, b0, b1);
            }
        }

        __syncthreads();  // stage fully consumed before refill

        if (kt + 2 < NKT) {
            issue_kv(kt + 2);
            CP_COMMIT();
        }
    }

    // ---- epilogue: normalize, write ctx fp16 [B,S,D] ----
    const float inv0 = 1.f / l0;
    const float inv1 = 1.f / l1;
    const int row0 = q0 + wq0 + g;
    const int row1 = row0 + 8;
    __half* out0 = g_ctxh + (size_t)(b * SEQ + row0) * DMODEL + h * 64;
    __half* out1 = g_ctxh + (size_t)(b * SEQ + row1) * DMODEL + h * 64;
#pragma unroll
    for (int nt = 0; nt < 8; nt++) {
        const int c = nt * 8 + 2 * q;
        __half2 v0 = __floats2half2_rn(o[nt][0] * inv0, o[nt][1] * inv0);
        __half2 v1 = __floats2half2_rn(o[nt][2] * inv1, o[nt][3] * inv1);
        *(__half2*)&out0[c] = v0;
        *(__half2*)&out1[c] = v1;
    }
}

// ---------------- launch ------------------------------------------------------
extern "C" void kernel_launch(void* const* d_in, const int* in_sizes, int n_in,
                              void* d_out, int out_size)
{
    const float* x  = (const float*)d_in[0];
    const int* mask = (const int*)d_in[1];
    const float* wq = (const float*)d_in[2];
    const float* bq = (const float*)d_in[3];
    const float* wk = (const float*)d_in[4];
    const float* bk = (const float*)d_in[5];
    const float* wv = (const float*)d_in[6];
    const float* bv = (const float*)d_in[7];
    const float* wo = (const float*)d_in[8];
    const float* bo = (const float*)d_in[9];

    __half* d_xh;   cudaGetSymbolAddress((void**)&d_xh, g_xh);
    __half* d_wqt;  cudaGetSymbolAddress((void**)&d_wqt, g_wqt);
    __half* d_wkt;  cudaGetSymbolAddress((void**)&d_wkt, g_wkt);
    __half* d_wvt;  cudaGetSymbolAddress((void**)&d_wvt, g_wvt);
    __half* d_wot;  cudaGetSymbolAddress((void**)&d_wot, g_wot);

    const int nx4 = BATCH * SEQ * DMODEL / 4;
    cvt_f16_kernel<<<(nx4 + 255) / 256, 256>>>(x, d_xh, nx4);
    dim3 tg(DMODEL / 32, DMODEL / 32);
    cvt_transpose_kernel<<<tg, 256>>>(wq, d_wqt);
    cvt_transpose_kernel<<<tg, 256>>>(wk, d_wkt);
    cvt_transpose_kernel<<<tg, 256>>>(wv, d_wvt);
    cvt_transpose_kernel<<<tg, 256>>>(wo, d_wot);

    // 1) projections (fp16 mma)
    cudaFuncSetAttribute(qk_gemm_f16,
                         cudaFuncAttributeMaxDynamicSharedMemorySize, GSMEM);
    cudaFuncSetAttribute(v_gemm_f16,
                         cudaFuncAttributeMaxDynamicSharedMemorySize, GSMEM);
    dim3 gqk(DMODEL / 256, (BATCH * SEQ) / 128, 2);
    qk_gemm_f16<<<gqk, 256, GSMEM>>>(bq, bk);
    dim3 gv(DMODEL / 256, (BATCH * SEQ) / 128);
    v_gemm_f16<<<gv, 256, GSMEM>>>(bv);

    // 2) flash attention (fp16 mma)
    cudaFuncSetAttribute(flash_attn_f16,
                         cudaFuncAttributeMaxDynamicSharedMemorySize, ATT_SMEM_BYTES);
    flash_attn_f16<<<dim3(SEQ / 128, BATCH * NHEADS), 256, ATT_SMEM_BYTES>>>(mask);

    // 3) output projection (fp16 mma, fp32 out)
    cudaFuncSetAttribute(out_gemm_f16,
                         cudaFuncAttributeMaxDynamicSharedMemorySize, GSMEM);
    dim3 g3(DMODEL / 256, (BATCH * SEQ) / 128);
    out_gemm_f16<<<g3, 256, GSMEM>>>(bo, (float*)d_out);
}